// round 4
// baseline (speedup 1.0000x reference)
#include <cuda_runtime.h>
#include <cuda_bf16.h>
#include <math.h>

// Problem constants (fixed shapes for this bench)
#define NMAX 50000
#define EMAX 800000
#define D    128
#define C    32

// ---------------- scratch (device globals; no allocation allowed) ----------
__device__ float g_deg[NMAX];
__device__ float g_dis[NMAX];
__device__ int   g_cnt[NMAX];
__device__ int   g_off[NMAX + 1];
__device__ int   g_src[EMAX];
__device__ float g_nrm[EMAX];
__device__ float g_h1[(size_t)NMAX * D];   // emb[x] @ W1
__device__ float g_a1[(size_t)NMAX * D];   // relu(aggregate(h1) + b1)
__device__ float g_h2[(size_t)NMAX * C];   // a1 @ W2

// ---------------- kernel 1: init deg (self-loop weight 1) + counts ---------
__global__ void k_init(int n) {
    for (int i = blockIdx.x * blockDim.x + threadIdx.x; i < n;
         i += gridDim.x * blockDim.x) {
        g_deg[i] = 1.0f;   // self loop contributes weight 1 to in-degree
        g_cnt[i] = 0;
    }
}

// ---------------- kernel 2: degree accumulation + in-edge counts -----------
__global__ void k_deg(const int* __restrict__ row, const int* __restrict__ col,
                      const float* __restrict__ w, int e) {
    for (int i = blockIdx.x * blockDim.x + threadIdx.x; i < e;
         i += gridDim.x * blockDim.x) {
        int c = col[i];
        atomicAdd(&g_deg[c], w[i]);
        atomicAdd(&g_cnt[c], 1);
    }
}

// ---------------- kernel 3: single-block exclusive scan + dis --------------
__global__ void k_scan(int n) {
    __shared__ int s[1024];
    const int tid = threadIdx.x;
    const int CH = (n + 1023) / 1024;
    const int base = tid * CH;
    const int lim = min(base + CH, n);

    int sum = 0;
    for (int i = base; i < lim; i++) sum += g_cnt[i];
    s[tid] = sum;
    __syncthreads();
    // Hillis–Steele inclusive scan over 1024 partial sums
    for (int d = 1; d < 1024; d <<= 1) {
        int v = 0;
        if (tid >= d) v = s[tid - d];
        __syncthreads();
        if (tid >= d) s[tid] += v;
        __syncthreads();
    }
    int run = s[tid] - sum;  // exclusive prefix for this chunk
    for (int i = base; i < lim; i++) {
        int c = g_cnt[i];
        g_off[i] = run;
        run += c;
        g_cnt[i] = 0;                      // reuse as scatter cursor
        g_dis[i] = rsqrtf(g_deg[i]);       // deg >= 1 always (self loop)
    }
    if (tid == 1023) g_off[n] = run;       // == E
}

// ---------------- kernel 4: scatter edges into CSR-by-destination ----------
__global__ void k_scatter(const int* __restrict__ row, const int* __restrict__ col,
                          const float* __restrict__ w, int e) {
    for (int i = blockIdx.x * blockDim.x + threadIdx.x; i < e;
         i += gridDim.x * blockDim.x) {
        int r = row[i];
        int c = col[i];
        int pos = g_off[c] + atomicAdd(&g_cnt[c], 1);
        g_src[pos] = r;
        g_nrm[pos] = g_dis[r] * w[i] * g_dis[c];
    }
}

// ---------------- kernel 5: fused embedding gather + GEMM1 (D x D) ---------
// 128 threads/block, 32 nodes/block. W1 (64KB) + 32 emb rows (16KB) in smem.
// quad = tid&31 owns columns [4*quad, 4*quad+4) (exactly D=128 columns).
// ngrp = tid>>5 owns 8 nodes -> 8 float4 accumulators amortize W1 reads 8x.
// Within a warp all lanes share ngrp, so rows[] reads broadcast (no conflict).
#define G1_NODES 32
#define G1_SMEM ((D * D + G1_NODES * D) * sizeof(float))
__global__ void __launch_bounds__(128, 1)
k_gemm1(const int* __restrict__ x, const float* __restrict__ emb,
        const float* __restrict__ W1, int n) {
    extern __shared__ float sm[];
    float* Ws = sm;                 // [D*D]
    float* rows = sm + D * D;       // [G1_NODES * D]
    const int tid  = threadIdx.x;
    const int quad = tid & 31;      // column group
    const int ngrp = tid >> 5;      // node group (8 nodes)
    const int n0 = blockIdx.x * G1_NODES;

    // load W1 (row-major) cooperatively, float4
    const float4* W4 = (const float4*)W1;
    float4* Ws4 = (float4*)Ws;
    #pragma unroll
    for (int i = tid; i < D * D / 4; i += 128) Ws4[i] = W4[i];

    // gather embedding rows (float4 granularity): 32 rows x 32 float4
    float4* rows4 = (float4*)rows;
    for (int idx = tid; idx < G1_NODES * (D / 4); idx += 128) {
        int nl = idx >> 5;       // /32  -> local node
        int q  = idx & 31;       // float4 index within row
        int node = n0 + nl;
        float4 v = make_float4(0.f, 0.f, 0.f, 0.f);
        if (node < n)
            v = ((const float4*)&emb[(size_t)x[node] * D])[q];
        rows4[idx] = v;
    }
    __syncthreads();

    float4 acc[8];
    #pragma unroll
    for (int i = 0; i < 8; i++) acc[i] = make_float4(0.f, 0.f, 0.f, 0.f);

    #pragma unroll 4
    for (int k = 0; k < D; k++) {
        float4 wv = *(const float4*)&Ws[k * D + 4 * quad];
        #pragma unroll
        for (int j = 0; j < 8; j++) {
            float xv = rows[(ngrp * 8 + j) * D + k];
            acc[j].x = fmaf(xv, wv.x, acc[j].x);
            acc[j].y = fmaf(xv, wv.y, acc[j].y);
            acc[j].z = fmaf(xv, wv.z, acc[j].z);
            acc[j].w = fmaf(xv, wv.w, acc[j].w);
        }
    }
    #pragma unroll
    for (int j = 0; j < 8; j++) {
        int node = n0 + ngrp * 8 + j;
        if (node < n)
            *(float4*)&g_h1[(size_t)node * D + 4 * quad] = acc[j];
    }
}

// ---------------- kernel 6: aggregation 1 + bias + relu (gather) -----------
// One warp per node; lane owns float4 columns [4*lane, 4*lane+4).
__global__ void k_agg1(const float* __restrict__ b1, int n) {
    int warp = (blockIdx.x * blockDim.x + threadIdx.x) >> 5;
    int lane = threadIdx.x & 31;
    if (warp >= n) return;
    const int node = warp;

    float sn = g_dis[node] * g_dis[node];  // self-loop norm
    float4 acc = *(const float4*)&g_h1[(size_t)node * D + 4 * lane];
    acc.x *= sn; acc.y *= sn; acc.z *= sn; acc.w *= sn;

    int s0 = g_off[node], s1 = g_off[node + 1];
    for (int e = s0; e < s1; e++) {
        int src = __ldg(&g_src[e]);
        float nm = __ldg(&g_nrm[e]);
        float4 v = *(const float4*)&g_h1[(size_t)src * D + 4 * lane];
        acc.x = fmaf(nm, v.x, acc.x);
        acc.y = fmaf(nm, v.y, acc.y);
        acc.z = fmaf(nm, v.z, acc.z);
        acc.w = fmaf(nm, v.w, acc.w);
    }
    float4 bv = *(const float4*)&b1[4 * lane];
    acc.x = fmaxf(acc.x + bv.x, 0.f);
    acc.y = fmaxf(acc.y + bv.y, 0.f);
    acc.z = fmaxf(acc.z + bv.z, 0.f);
    acc.w = fmaxf(acc.w + bv.w, 0.f);
    *(float4*)&g_a1[(size_t)node * D + 4 * lane] = acc;
}

// ---------------- kernel 7: GEMM2 (D -> C), warp per node ------------------
__global__ void k_gemm2(const float* __restrict__ W2, int n) {
    __shared__ float W2s[D * C];        // 16KB
    __shared__ float rows[8][D];        // 4KB, one row per warp
    const int tid = threadIdx.x;
    const int wlocal = tid >> 5;
    const int lane = tid & 31;

    for (int i = tid; i < D * C; i += 256) W2s[i] = W2[i];

    int node = blockIdx.x * 8 + wlocal;
    if (node < n) {
        #pragma unroll
        for (int j = 0; j < D / 32; j++)
            rows[wlocal][lane + 32 * j] = g_a1[(size_t)node * D + lane + 32 * j];
    }
    __syncthreads();
    if (node >= n) return;

    float acc = 0.f;
    #pragma unroll 8
    for (int k = 0; k < D; k++)
        acc = fmaf(rows[wlocal][k], W2s[k * C + lane], acc);
    g_h2[(size_t)node * C + lane] = acc;
}

// ---------------- kernel 8: aggregation 2 + bias + log_softmax -------------
// One warp per node; lane == class (C == 32 exactly).
__global__ void k_agg2(const float* __restrict__ b2, float* __restrict__ out, int n) {
    int warp = (blockIdx.x * blockDim.x + threadIdx.x) >> 5;
    int lane = threadIdx.x & 31;
    if (warp >= n) return;
    const int node = warp;

    float sn = g_dis[node] * g_dis[node];
    float acc = g_h2[(size_t)node * C + lane] * sn;

    int s0 = g_off[node], s1 = g_off[node + 1];
    for (int e = s0; e < s1; e++) {
        int src = __ldg(&g_src[e]);
        float nm = __ldg(&g_nrm[e]);
        acc = fmaf(nm, g_h2[(size_t)src * C + lane], acc);
    }
    acc += b2[lane];

    // log_softmax over the warp (32 classes)
    float m = acc;
    #pragma unroll
    for (int o = 16; o > 0; o >>= 1)
        m = fmaxf(m, __shfl_xor_sync(0xFFFFFFFFu, m, o));
    float ex = expf(acc - m);
    float s = ex;
    #pragma unroll
    for (int o = 16; o > 0; o >>= 1)
        s += __shfl_xor_sync(0xFFFFFFFFu, s, o);
    out[(size_t)node * C + lane] = acc - m - logf(s);
}

// ---------------- launch ----------------------------------------------------
extern "C" void kernel_launch(void* const* d_in, const int* in_sizes, int n_in,
                              void* d_out, int out_size) {
    const int*   x   = (const int*)d_in[0];
    const int*   ei  = (const int*)d_in[1];
    const float* ew  = (const float*)d_in[2];
    const float* emb = (const float*)d_in[3];
    const float* W1  = (const float*)d_in[4];
    const float* b1  = (const float*)d_in[5];
    const float* W2  = (const float*)d_in[6];
    const float* b2  = (const float*)d_in[7];
    float* out = (float*)d_out;

    const int n = in_sizes[0];          // 50000
    const int e = in_sizes[2];          // 800000
    const int* row = ei;
    const int* col = ei + e;

    cudaFuncSetAttribute((const void*)k_gemm1,
                         cudaFuncAttributeMaxDynamicSharedMemorySize,
                         (int)G1_SMEM);

    int gN = (n + 255) / 256;
    int gE = (e + 255) / 256;
    int gW = (n + 7) / 8;               // 8 warps/block, warp-per-node kernels

    k_init<<<gN, 256>>>(n);
    k_deg<<<gE, 256>>>(row, col, ew, e);
    k_scan<<<1, 1024>>>(n);
    k_scatter<<<gE, 256>>>(row, col, ew, e);
    k_gemm1<<<(n + G1_NODES - 1) / G1_NODES, 128, G1_SMEM>>>(x, emb, W1, n);
    k_agg1<<<gW, 256>>>(b1, n);
    k_gemm2<<<gW, 256>>>(W2, n);
    k_agg2<<<gW, 256>>>(b2, out, n);
}

// round 5
// speedup vs baseline: 1.4018x; 1.4018x over previous
#include <cuda_runtime.h>
#include <cuda_bf16.h>
#include <math.h>

// Problem constants (fixed shapes for this bench)
#define NMAX 50000
#define EMAX 800000
#define D    128
#define C    32

// ---------------- scratch (device globals; no allocation allowed) ----------
__device__ float g_dis[NMAX];
__device__ int   g_cnt[NMAX];
__device__ int   g_off[NMAX + 1];
__device__ uint2 g_edge[EMAX];             // {src, bit_cast<uint>(w)}
__device__ float g_h1[(size_t)NMAX * D];   // emb[x] @ W1
__device__ float g_h2[(size_t)NMAX * C];   // relu(agg1)+b1 @ W2  (pre-agg2)

// ---------------- packed f32x2 helpers (sm_103a FFMA2) ---------------------
__device__ __forceinline__ unsigned long long fma2(unsigned long long a,
                                                   unsigned long long b,
                                                   unsigned long long c) {
    unsigned long long d;
    asm("fma.rn.f32x2 %0, %1, %2, %3;" : "=l"(d) : "l"(a), "l"(b), "l"(c));
    return d;
}
__device__ __forceinline__ unsigned long long splat2(float x) {
    unsigned long long d;
    unsigned int b = __float_as_uint(x);
    asm("mov.b64 %0, {%1, %1};" : "=l"(d) : "r"(b));
    return d;
}
__device__ __forceinline__ unsigned long long pack2(float lo, float hi) {
    unsigned long long d;
    asm("mov.b64 %0, {%1, %2};" : "=l"(d) : "f"(lo), "f"(hi));
    return d;
}
__device__ __forceinline__ float lo2(unsigned long long v) {
    return __uint_as_float((unsigned int)v);
}
__device__ __forceinline__ float hi2(unsigned long long v) {
    return __uint_as_float((unsigned int)(v >> 32));
}

// ---------------- kernel 1: zero counts ------------------------------------
__global__ void k_init(int n) {
    for (int i = blockIdx.x * blockDim.x + threadIdx.x; i < n;
         i += gridDim.x * blockDim.x)
        g_cnt[i] = 0;
}

// ---------------- kernel 2: in-edge counts (one int atomic per edge) -------
__global__ void k_cnt(const int* __restrict__ col, int e) {
    for (int i = blockIdx.x * blockDim.x + threadIdx.x; i < e;
         i += gridDim.x * blockDim.x)
        atomicAdd(&g_cnt[col[i]], 1);
}

// ---------------- kernel 3: single-block exclusive scan --------------------
__global__ void k_scan(int n) {
    __shared__ int s[1024];
    const int tid = threadIdx.x;
    const int CH = (n + 1023) / 1024;
    const int base = tid * CH;
    const int lim = min(base + CH, n);

    int sum = 0;
    for (int i = base; i < lim; i++) sum += g_cnt[i];
    s[tid] = sum;
    __syncthreads();
    for (int d = 1; d < 1024; d <<= 1) {
        int v = 0;
        if (tid >= d) v = s[tid - d];
        __syncthreads();
        if (tid >= d) s[tid] += v;
        __syncthreads();
    }
    int run = s[tid] - sum;  // exclusive prefix for this chunk
    for (int i = base; i < lim; i++) {
        int c = g_cnt[i];
        g_off[i] = run;
        run += c;
        g_cnt[i] = 0;                      // reuse as scatter cursor
    }
    if (tid == 1023) g_off[n] = run;       // == E
}

// ---------------- kernel 4: scatter packed edges into CSR-by-dest ----------
__global__ void k_scatter(const int* __restrict__ row, const int* __restrict__ col,
                          const float* __restrict__ w, int e) {
    for (int i = blockIdx.x * blockDim.x + threadIdx.x; i < e;
         i += gridDim.x * blockDim.x) {
        int c = col[i];
        int pos = g_off[c] + atomicAdd(&g_cnt[c], 1);
        g_edge[pos] = make_uint2((unsigned)row[i], __float_as_uint(w[i]));
    }
}

// ---------------- kernel 5: degree sum (coalesced) + rsqrt -----------------
__global__ void k_degdis(int n) {
    int warp = (blockIdx.x * blockDim.x + threadIdx.x) >> 5;
    int lane = threadIdx.x & 31;
    if (warp >= n) return;
    int s0 = g_off[warp], s1 = g_off[warp + 1];
    float s = 0.f;
    for (int e = s0 + lane; e < s1; e += 32)
        s += __uint_as_float(__ldg(&g_edge[e]).y);
    #pragma unroll
    for (int o = 16; o > 0; o >>= 1)
        s += __shfl_xor_sync(0xFFFFFFFFu, s, o);
    if (lane == 0) g_dis[warp] = rsqrtf(1.0f + s);   // self-loop weight 1
}

// ---------------- kernel 6: fused embedding gather + GEMM1 (f32x2) ---------
// 256 threads/block, 64 nodes/tile, grid-stride over tiles (W1 loaded once).
// quad = tid&31 owns cols [4q,4q+4); ngrp = tid>>5 owns 8 nodes.
#define G1_NODES 64
#define G1_SMEM ((D * D + G1_NODES * D) * sizeof(float))
__global__ void __launch_bounds__(256, 2)
k_gemm1(const int* __restrict__ x, const float* __restrict__ emb,
        const float* __restrict__ W1, int n) {
    extern __shared__ float sm[];
    float* Ws = sm;                 // [D*D]  (64KB)
    float* rows = sm + D * D;       // [64*D] (32KB)
    const int tid  = threadIdx.x;
    const int quad = tid & 31;
    const int ngrp = tid >> 5;

    // load W1 once per block (float4)
    const float4* W4 = (const float4*)W1;
    float4* Ws4 = (float4*)Ws;
    #pragma unroll
    for (int i = tid; i < D * D / 4; i += 256) Ws4[i] = W4[i];

    bool first = true;
    for (int n0 = blockIdx.x * G1_NODES; n0 < n; n0 += gridDim.x * G1_NODES) {
        if (!first) __syncthreads();   // protect rows from previous tile's readers
        first = false;

        // gather embedding rows: 64 rows x 32 float4
        float4* rows4 = (float4*)rows;
        #pragma unroll
        for (int idx = tid; idx < G1_NODES * (D / 4); idx += 256) {
            int nl = idx >> 5;
            int q  = idx & 31;
            int node = n0 + nl;
            float4 v = make_float4(0.f, 0.f, 0.f, 0.f);
            if (node < n)
                v = ((const float4*)&emb[(size_t)__ldg(&x[node]) * D])[q];
            rows4[idx] = v;
        }
        __syncthreads();

        unsigned long long acc[8][2];
        #pragma unroll
        for (int j = 0; j < 8; j++) { acc[j][0] = 0ULL; acc[j][1] = 0ULL; }

        #pragma unroll 4
        for (int k = 0; k < D; k++) {
            ulonglong2 wv = *(const ulonglong2*)&Ws[k * D + 4 * quad];
            #pragma unroll
            for (int j = 0; j < 8; j++) {
                unsigned long long xs = splat2(rows[(ngrp * 8 + j) * D + k]);
                acc[j][0] = fma2(xs, wv.x, acc[j][0]);
                acc[j][1] = fma2(xs, wv.y, acc[j][1]);
            }
        }
        #pragma unroll
        for (int j = 0; j < 8; j++) {
            int node = n0 + ngrp * 8 + j;
            if (node < n)
                *(ulonglong2*)&g_h1[(size_t)node * D + 4 * quad] =
                    make_ulonglong2(acc[j][0], acc[j][1]);
        }
    }
}

// ---------------- kernel 7: agg1 + bias + relu + GEMM2 (fused) -------------
// Warp per node (grid-stride). W2 packed as f32x2 k-pairs in smem (once/block).
__global__ void __launch_bounds__(256)
k_agg1g2(const float* __restrict__ b1, const float* __restrict__ W2, int n) {
    __shared__ unsigned long long W2p[(D / 2) * C];   // 16KB
    __shared__ __align__(16) float rowsm[8][D];       // 4KB (one row per warp)
    const int tid = threadIdx.x;
    const int wl = tid >> 5;
    const int lane = tid & 31;

    // pack W2 k-pairs: W2p[kk*32+c] = (W2[2kk][c], W2[2kk+1][c])
    for (int i = tid; i < (D / 2) * C; i += 256) {
        int kk = i >> 5, c = i & 31;
        W2p[i] = pack2(W2[(2 * kk) * C + c], W2[(2 * kk + 1) * C + c]);
    }
    __syncthreads();

    float4 bv = *(const float4*)&b1[4 * lane];

    for (int node = blockIdx.x * 8 + wl; node < n; node += gridDim.x * 8) {
        float dn = __ldg(&g_dis[node]);
        float4 acc = *(const float4*)&g_h1[(size_t)node * D + 4 * lane];
        acc.x *= dn; acc.y *= dn; acc.z *= dn; acc.w *= dn;   // self term (dn applied again at end)

        int s0 = g_off[node], s1 = g_off[node + 1];
        for (int e = s0; e < s1; e++) {
            uint2 ev = __ldg(&g_edge[e]);
            float nm = __ldg(&g_dis[ev.x]) * __uint_as_float(ev.y);
            float4 v = *(const float4*)&g_h1[(size_t)ev.x * D + 4 * lane];
            acc.x = fmaf(nm, v.x, acc.x);
            acc.y = fmaf(nm, v.y, acc.y);
            acc.z = fmaf(nm, v.z, acc.z);
            acc.w = fmaf(nm, v.w, acc.w);
        }
        // final dn scale + bias + relu
        acc.x = fmaxf(fmaf(dn, acc.x, bv.x), 0.f);
        acc.y = fmaxf(fmaf(dn, acc.y, bv.y), 0.f);
        acc.z = fmaxf(fmaf(dn, acc.z, bv.z), 0.f);
        acc.w = fmaxf(fmaf(dn, acc.w, bv.w), 0.f);

        // write row to smem, then warp-wide dot against W2 (f32x2 pairs)
        *(float4*)&rowsm[wl][4 * lane] = acc;
        __syncwarp();

        const unsigned long long* rp = (const unsigned long long*)rowsm[wl];
        unsigned long long a0 = 0ULL, a1 = 0ULL;
        #pragma unroll 8
        for (int kk = 0; kk < D / 2; kk += 2) {
            a0 = fma2(rp[kk],     W2p[kk * C + lane],       a0);
            a1 = fma2(rp[kk + 1], W2p[(kk + 1) * C + lane], a1);
        }
        __syncwarp();   // row consumed; safe to overwrite next iteration
        float h2 = lo2(a0) + hi2(a0) + lo2(a1) + hi2(a1);
        g_h2[(size_t)node * C + lane] = h2;
    }
}

// ---------------- kernel 8: agg2 + bias + log_softmax ----------------------
// One warp per node; lane == class (C == 32 exactly).
__global__ void k_agg2(const float* __restrict__ b2, float* __restrict__ out, int n) {
    int warp = (blockIdx.x * blockDim.x + threadIdx.x) >> 5;
    int lane = threadIdx.x & 31;
    if (warp >= n) return;
    const int node = warp;

    float dn = __ldg(&g_dis[node]);
    float acc = dn * g_h2[(size_t)node * C + lane];

    int s0 = g_off[node], s1 = g_off[node + 1];
    for (int e = s0; e < s1; e++) {
        uint2 ev = __ldg(&g_edge[e]);
        float nm = __ldg(&g_dis[ev.x]) * __uint_as_float(ev.y);
        acc = fmaf(nm, g_h2[(size_t)ev.x * C + lane], acc);
    }
    acc = fmaf(dn, acc, b2[lane]);

    // log_softmax over the warp (32 classes)
    float m = acc;
    #pragma unroll
    for (int o = 16; o > 0; o >>= 1)
        m = fmaxf(m, __shfl_xor_sync(0xFFFFFFFFu, m, o));
    float ex = __expf(acc - m);
    float s = ex;
    #pragma unroll
    for (int o = 16; o > 0; o >>= 1)
        s += __shfl_xor_sync(0xFFFFFFFFu, s, o);
    out[(size_t)node * C + lane] = acc - m - __logf(s);
}

// ---------------- launch ----------------------------------------------------
extern "C" void kernel_launch(void* const* d_in, const int* in_sizes, int n_in,
                              void* d_out, int out_size) {
    const int*   x   = (const int*)d_in[0];
    const int*   ei  = (const int*)d_in[1];
    const float* ew  = (const float*)d_in[2];
    const float* emb = (const float*)d_in[3];
    const float* W1  = (const float*)d_in[4];
    const float* b1  = (const float*)d_in[5];
    const float* W2  = (const float*)d_in[6];
    const float* b2  = (const float*)d_in[7];
    float* out = (float*)d_out;

    const int n = in_sizes[0];          // 50000
    const int e = in_sizes[2];          // 800000
    const int* row = ei;
    const int* col = ei + e;

    cudaFuncSetAttribute((const void*)k_gemm1,
                         cudaFuncAttributeMaxDynamicSharedMemorySize,
                         (int)G1_SMEM);

    int gN = (n + 255) / 256;
    int gE = (e + 255) / 256;
    int gW = (n + 7) / 8;               // 8 warps/block, warp-per-node kernels

    k_init<<<gN, 256>>>(n);
    k_cnt<<<gE, 256>>>(col, e);
    k_scan<<<1, 1024>>>(n);
    k_scatter<<<gE, 256>>>(row, col, ew, e);
    k_degdis<<<gW, 256>>>(n);
    k_gemm1<<<296, 256, G1_SMEM>>>(x, emb, W1, n);      // 2 blocks/SM, grid-stride
    k_agg1g2<<<1480, 256>>>(b1, W2, n);                 // grid-stride warp/node
    k_agg2<<<gW, 256>>>(b2, out, n);
}

// round 6
// speedup vs baseline: 1.8876x; 1.3466x over previous
#include <cuda_runtime.h>
#include <cuda_bf16.h>
#include <math.h>

// Problem constants (fixed shapes for this bench)
#define NMAX 50000
#define EMAX 800000
#define D    128
#define C    32
#define SCAN_TILE 1024
#define SCAN_MAXB 64   // ceil(NMAX/1024)=49 <= 64

// ---------------- scratch (device globals; no allocation allowed) ----------
__device__ float g_dis[NMAX];
__device__ int   g_cnt[NMAX];
__device__ int   g_off[NMAX + 1];
__device__ int   g_bsum[SCAN_MAXB];
__device__ int   g_bpre[SCAN_MAXB];
__device__ uint2 g_edge[EMAX];             // {src, bit_cast<uint>(w)}
__device__ float g_h1[(size_t)NMAX * D];   // emb[x] @ W1
__device__ float g_h2[(size_t)NMAX * C];   // relu(agg1)+b1 @ W2  (pre-agg2)

// ---------------- packed f32x2 helpers (sm_103a FFMA2) ---------------------
__device__ __forceinline__ unsigned long long fma2(unsigned long long a,
                                                   unsigned long long b,
                                                   unsigned long long c) {
    unsigned long long d;
    asm("fma.rn.f32x2 %0, %1, %2, %3;" : "=l"(d) : "l"(a), "l"(b), "l"(c));
    return d;
}
__device__ __forceinline__ unsigned long long splat2(float x) {
    unsigned long long d;
    unsigned int b = __float_as_uint(x);
    asm("mov.b64 %0, {%1, %1};" : "=l"(d) : "r"(b));
    return d;
}
__device__ __forceinline__ unsigned long long pack2(float lo, float hi) {
    unsigned long long d;
    asm("mov.b64 %0, {%1, %2};" : "=l"(d) : "f"(lo), "f"(hi));
    return d;
}
__device__ __forceinline__ float lo2(unsigned long long v) {
    return __uint_as_float((unsigned int)v);
}
__device__ __forceinline__ float hi2(unsigned long long v) {
    return __uint_as_float((unsigned int)(v >> 32));
}

// ---------------- kernel 1: zero counts ------------------------------------
__global__ void k_init(int n) {
    for (int i = blockIdx.x * blockDim.x + threadIdx.x; i < n;
         i += gridDim.x * blockDim.x)
        g_cnt[i] = 0;
}

// ---------------- kernel 2: in-edge counts (one int atomic per edge) -------
__global__ void k_cnt(const int* __restrict__ col, int e) {
    for (int i = blockIdx.x * blockDim.x + threadIdx.x; i < e;
         i += gridDim.x * blockDim.x)
        atomicAdd(&g_cnt[col[i]], 1);
}

// ---------------- kernel 3a: per-block scan of 1024 counts (int4+shfl) -----
__global__ void k_scan1(int n) {
    __shared__ int wsum[8];
    const int tid = threadIdx.x;           // 256 threads
    const int lane = tid & 31, w = tid >> 5;
    const int base = (blockIdx.x * 256 + tid) * 4;

    int4 c = make_int4(0, 0, 0, 0);
    if (base + 3 < n) {
        c = *(const int4*)&g_cnt[base];
    } else if (base < n) {
        c.x = g_cnt[base];
        if (base + 1 < n) c.y = g_cnt[base + 1];
        if (base + 2 < n) c.z = g_cnt[base + 2];
    }
    int s = c.x + c.y + c.z + c.w;

    // inclusive warp scan of per-thread sums
    int v = s;
    #pragma unroll
    for (int o = 1; o < 32; o <<= 1) {
        int t = __shfl_up_sync(0xFFFFFFFFu, v, o);
        if (lane >= o) v += t;
    }
    if (lane == 31) wsum[w] = v;
    __syncthreads();
    if (w == 0) {
        int ws = (lane < 8) ? wsum[lane] : 0;
        #pragma unroll
        for (int o = 1; o < 8; o <<= 1) {
            int t = __shfl_up_sync(0xFFFFFFFFu, ws, o);
            if (lane >= o) ws += t;
        }
        if (lane < 8) wsum[lane] = ws;
    }
    __syncthreads();

    int excl = v - s + (w > 0 ? wsum[w - 1] : 0);
    int o0 = excl, o1 = o0 + c.x, o2 = o1 + c.y, o3 = o2 + c.z;
    if (base + 3 < n) {
        *(int4*)&g_off[base] = make_int4(o0, o1, o2, o3);
        *(int4*)&g_cnt[base] = make_int4(0, 0, 0, 0);   // reuse as cursor
    } else if (base < n) {
        g_off[base] = o0; g_cnt[base] = 0;
        if (base + 1 < n) { g_off[base + 1] = o1; g_cnt[base + 1] = 0; }
        if (base + 2 < n) { g_off[base + 2] = o2; g_cnt[base + 2] = 0; }
    }
    if (tid == 255) g_bsum[blockIdx.x] = wsum[7];       // block total
}

// ---------------- kernel 3b: scan block sums (single small block) ----------
__global__ void k_scan2(int nb, int n) {
    __shared__ int s[SCAN_MAXB];
    const int tid = threadIdx.x;            // 64 threads
    int v = (tid < nb) ? g_bsum[tid] : 0;
    s[tid] = v;
    __syncthreads();
    for (int d = 1; d < SCAN_MAXB; d <<= 1) {
        int t = 0;
        if (tid >= d) t = s[tid - d];
        __syncthreads();
        if (tid >= d) s[tid] += t;
        __syncthreads();
    }
    if (tid < nb) g_bpre[tid] = s[tid] - v;  // exclusive prefix
    if (tid == SCAN_MAXB - 1) g_off[n] = s[SCAN_MAXB - 1];  // == E
}

// ---------------- kernel 3c: add block prefixes ------------------------------
__global__ void k_scan3(int n) {
    int add = g_bpre[blockIdx.x];
    if (add == 0) return;
    int base = (blockIdx.x * 256 + threadIdx.x) * 4;
    if (base + 3 < n) {
        int4 o = *(int4*)&g_off[base];
        o.x += add; o.y += add; o.z += add; o.w += add;
        *(int4*)&g_off[base] = o;
    } else if (base < n) {
        g_off[base] += add;
        if (base + 1 < n) g_off[base + 1] += add;
        if (base + 2 < n) g_off[base + 2] += add;
    }
}

// ---------------- kernel 4: scatter packed edges into CSR-by-dest ----------
__global__ void k_scatter(const int* __restrict__ row, const int* __restrict__ col,
                          const float* __restrict__ w, int e) {
    for (int i = blockIdx.x * blockDim.x + threadIdx.x; i < e;
         i += gridDim.x * blockDim.x) {
        int c = col[i];
        int pos = g_off[c] + atomicAdd(&g_cnt[c], 1);
        g_edge[pos] = make_uint2((unsigned)row[i], __float_as_uint(w[i]));
    }
}

// ---------------- kernel 5: degree sum (coalesced) + rsqrt -----------------
__global__ void k_degdis(int n) {
    int warp = (blockIdx.x * blockDim.x + threadIdx.x) >> 5;
    int lane = threadIdx.x & 31;
    if (warp >= n) return;
    int s0 = g_off[warp], s1 = g_off[warp + 1];
    float s = 0.f;
    for (int e = s0 + lane; e < s1; e += 32)
        s += __uint_as_float(__ldg(&g_edge[e]).y);
    #pragma unroll
    for (int o = 16; o > 0; o >>= 1)
        s += __shfl_xor_sync(0xFFFFFFFFu, s, o);
    if (lane == 0) g_dis[warp] = rsqrtf(1.0f + s);   // self-loop weight 1
}

// ---------------- kernel 6: fused embedding gather + GEMM1 (f32x2) ---------
#define G1_NODES 64
#define G1_SMEM ((D * D + G1_NODES * D) * sizeof(float))
__global__ void __launch_bounds__(256, 2)
k_gemm1(const int* __restrict__ x, const float* __restrict__ emb,
        const float* __restrict__ W1, int n) {
    extern __shared__ float sm[];
    float* Ws = sm;                 // [D*D]  (64KB)
    float* rows = sm + D * D;       // [64*D] (32KB)
    const int tid  = threadIdx.x;
    const int quad = tid & 31;
    const int ngrp = tid >> 5;

    const float4* W4 = (const float4*)W1;
    float4* Ws4 = (float4*)Ws;
    #pragma unroll
    for (int i = tid; i < D * D / 4; i += 256) Ws4[i] = W4[i];

    bool first = true;
    for (int n0 = blockIdx.x * G1_NODES; n0 < n; n0 += gridDim.x * G1_NODES) {
        if (!first) __syncthreads();
        first = false;

        float4* rows4 = (float4*)rows;
        #pragma unroll
        for (int idx = tid; idx < G1_NODES * (D / 4); idx += 256) {
            int nl = idx >> 5;
            int q  = idx & 31;
            int node = n0 + nl;
            float4 v = make_float4(0.f, 0.f, 0.f, 0.f);
            if (node < n)
                v = ((const float4*)&emb[(size_t)__ldg(&x[node]) * D])[q];
            rows4[idx] = v;
        }
        __syncthreads();

        unsigned long long acc[8][2];
        #pragma unroll
        for (int j = 0; j < 8; j++) { acc[j][0] = 0ULL; acc[j][1] = 0ULL; }

        #pragma unroll 4
        for (int k = 0; k < D; k++) {
            ulonglong2 wv = *(const ulonglong2*)&Ws[k * D + 4 * quad];
            #pragma unroll
            for (int j = 0; j < 8; j++) {
                unsigned long long xs = splat2(rows[(ngrp * 8 + j) * D + k]);
                acc[j][0] = fma2(xs, wv.x, acc[j][0]);
                acc[j][1] = fma2(xs, wv.y, acc[j][1]);
            }
        }
        #pragma unroll
        for (int j = 0; j < 8; j++) {
            int node = n0 + ngrp * 8 + j;
            if (node < n)
                *(ulonglong2*)&g_h1[(size_t)node * D + 4 * quad] =
                    make_ulonglong2(acc[j][0], acc[j][1]);
        }
    }
}

// ---------------- kernel 7: agg1 + bias + relu + GEMM2 (fused, MLP=4) ------
__global__ void __launch_bounds__(256)
k_agg1g2(const float* __restrict__ b1, const float* __restrict__ W2, int n) {
    __shared__ unsigned long long W2p[(D / 2) * C];   // 16KB
    __shared__ __align__(16) float rowsm[8][D];       // 4KB
    const int tid = threadIdx.x;
    const int wl = tid >> 5;
    const int lane = tid & 31;

    for (int i = tid; i < (D / 2) * C; i += 256) {
        int kk = i >> 5, c = i & 31;
        W2p[i] = pack2(W2[(2 * kk) * C + c], W2[(2 * kk + 1) * C + c]);
    }
    __syncthreads();

    float4 bv = *(const float4*)&b1[4 * lane];

    for (int node = blockIdx.x * 8 + wl; node < n; node += gridDim.x * 8) {
        float dn = __ldg(&g_dis[node]);
        float4 acc = *(const float4*)&g_h1[(size_t)node * D + 4 * lane];
        acc.x *= dn; acc.y *= dn; acc.z *= dn; acc.w *= dn;

        int s0 = g_off[node], s1 = g_off[node + 1];
        int e = s0;
        for (; e + 4 <= s1; e += 4) {   // MLP=4: batch independent loads
            uint2 e0 = __ldg(&g_edge[e]);
            uint2 e1 = __ldg(&g_edge[e + 1]);
            uint2 e2 = __ldg(&g_edge[e + 2]);
            uint2 e3 = __ldg(&g_edge[e + 3]);
            float n0 = __ldg(&g_dis[e0.x]) * __uint_as_float(e0.y);
            float n1 = __ldg(&g_dis[e1.x]) * __uint_as_float(e1.y);
            float n2 = __ldg(&g_dis[e2.x]) * __uint_as_float(e2.y);
            float n3 = __ldg(&g_dis[e3.x]) * __uint_as_float(e3.y);
            float4 v0 = *(const float4*)&g_h1[(size_t)e0.x * D + 4 * lane];
            float4 v1 = *(const float4*)&g_h1[(size_t)e1.x * D + 4 * lane];
            float4 v2 = *(const float4*)&g_h1[(size_t)e2.x * D + 4 * lane];
            float4 v3 = *(const float4*)&g_h1[(size_t)e3.x * D + 4 * lane];
            acc.x = fmaf(n0, v0.x, acc.x); acc.y = fmaf(n0, v0.y, acc.y);
            acc.z = fmaf(n0, v0.z, acc.z); acc.w = fmaf(n0, v0.w, acc.w);
            acc.x = fmaf(n1, v1.x, acc.x); acc.y = fmaf(n1, v1.y, acc.y);
            acc.z = fmaf(n1, v1.z, acc.z); acc.w = fmaf(n1, v1.w, acc.w);
            acc.x = fmaf(n2, v2.x, acc.x); acc.y = fmaf(n2, v2.y, acc.y);
            acc.z = fmaf(n2, v2.z, acc.z); acc.w = fmaf(n2, v2.w, acc.w);
            acc.x = fmaf(n3, v3.x, acc.x); acc.y = fmaf(n3, v3.y, acc.y);
            acc.z = fmaf(n3, v3.z, acc.z); acc.w = fmaf(n3, v3.w, acc.w);
        }
        for (; e < s1; e++) {
            uint2 ev = __ldg(&g_edge[e]);
            float nm = __ldg(&g_dis[ev.x]) * __uint_as_float(ev.y);
            float4 v = *(const float4*)&g_h1[(size_t)ev.x * D + 4 * lane];
            acc.x = fmaf(nm, v.x, acc.x);
            acc.y = fmaf(nm, v.y, acc.y);
            acc.z = fmaf(nm, v.z, acc.z);
            acc.w = fmaf(nm, v.w, acc.w);
        }
        acc.x = fmaxf(fmaf(dn, acc.x, bv.x), 0.f);
        acc.y = fmaxf(fmaf(dn, acc.y, bv.y), 0.f);
        acc.z = fmaxf(fmaf(dn, acc.z, bv.z), 0.f);
        acc.w = fmaxf(fmaf(dn, acc.w, bv.w), 0.f);

        *(float4*)&rowsm[wl][4 * lane] = acc;
        __syncwarp();

        const unsigned long long* rp = (const unsigned long long*)rowsm[wl];
        unsigned long long a0 = 0ULL, a1 = 0ULL;
        #pragma unroll 8
        for (int kk = 0; kk < D / 2; kk += 2) {
            a0 = fma2(rp[kk],     W2p[kk * C + lane],       a0);
            a1 = fma2(rp[kk + 1], W2p[(kk + 1) * C + lane], a1);
        }
        __syncwarp();
        float h2 = lo2(a0) + hi2(a0) + lo2(a1) + hi2(a1);
        g_h2[(size_t)node * C + lane] = h2;
    }
}

// ---------------- kernel 8: agg2 + bias + log_softmax (MLP=4) --------------
__global__ void k_agg2(const float* __restrict__ b2, float* __restrict__ out, int n) {
    int warp = (blockIdx.x * blockDim.x + threadIdx.x) >> 5;
    int lane = threadIdx.x & 31;
    if (warp >= n) return;
    const int node = warp;

    float dn = __ldg(&g_dis[node]);
    float acc = dn * g_h2[(size_t)node * C + lane];

    int s0 = g_off[node], s1 = g_off[node + 1];
    int e = s0;
    for (; e + 4 <= s1; e += 4) {
        uint2 e0 = __ldg(&g_edge[e]);
        uint2 e1 = __ldg(&g_edge[e + 1]);
        uint2 e2 = __ldg(&g_edge[e + 2]);
        uint2 e3 = __ldg(&g_edge[e + 3]);
        float n0 = __ldg(&g_dis[e0.x]) * __uint_as_float(e0.y);
        float n1 = __ldg(&g_dis[e1.x]) * __uint_as_float(e1.y);
        float n2 = __ldg(&g_dis[e2.x]) * __uint_as_float(e2.y);
        float n3 = __ldg(&g_dis[e3.x]) * __uint_as_float(e3.y);
        float v0 = g_h2[(size_t)e0.x * C + lane];
        float v1 = g_h2[(size_t)e1.x * C + lane];
        float v2 = g_h2[(size_t)e2.x * C + lane];
        float v3 = g_h2[(size_t)e3.x * C + lane];
        acc = fmaf(n0, v0, acc);
        acc = fmaf(n1, v1, acc);
        acc = fmaf(n2, v2, acc);
        acc = fmaf(n3, v3, acc);
    }
    for (; e < s1; e++) {
        uint2 ev = __ldg(&g_edge[e]);
        float nm = __ldg(&g_dis[ev.x]) * __uint_as_float(ev.y);
        acc = fmaf(nm, g_h2[(size_t)ev.x * C + lane], acc);
    }
    acc = fmaf(dn, acc, b2[lane]);

    float m = acc;
    #pragma unroll
    for (int o = 16; o > 0; o >>= 1)
        m = fmaxf(m, __shfl_xor_sync(0xFFFFFFFFu, m, o));
    float ex = __expf(acc - m);
    float s = ex;
    #pragma unroll
    for (int o = 16; o > 0; o >>= 1)
        s += __shfl_xor_sync(0xFFFFFFFFu, s, o);
    out[(size_t)node * C + lane] = acc - m - __logf(s);
}

// ---------------- launch ----------------------------------------------------
extern "C" void kernel_launch(void* const* d_in, const int* in_sizes, int n_in,
                              void* d_out, int out_size) {
    const int*   x   = (const int*)d_in[0];
    const int*   ei  = (const int*)d_in[1];
    const float* ew  = (const float*)d_in[2];
    const float* emb = (const float*)d_in[3];
    const float* W1  = (const float*)d_in[4];
    const float* b1  = (const float*)d_in[5];
    const float* W2  = (const float*)d_in[6];
    const float* b2  = (const float*)d_in[7];
    float* out = (float*)d_out;

    const int n = in_sizes[0];          // 50000
    const int e = in_sizes[2];          // 800000
    const int* row = ei;
    const int* col = ei + e;

    cudaFuncSetAttribute((const void*)k_gemm1,
                         cudaFuncAttributeMaxDynamicSharedMemorySize,
                         (int)G1_SMEM);

    int gN = (n + 255) / 256;
    int gE = (e + 255) / 256;
    int gW = (n + 7) / 8;                      // warp-per-node kernels
    int nb = (n + SCAN_TILE - 1) / SCAN_TILE;  // scan blocks (49)

    k_init<<<gN, 256>>>(n);
    k_cnt<<<gE, 256>>>(col, e);
    k_scan1<<<nb, 256>>>(n);
    k_scan2<<<1, SCAN_MAXB>>>(nb, n);
    k_scan3<<<nb, 256>>>(n);
    k_scatter<<<gE, 256>>>(row, col, ew, e);
    k_degdis<<<gW, 256>>>(n);
    k_gemm1<<<296, 256, G1_SMEM>>>(x, emb, W1, n);   // 2 blocks/SM, grid-stride
    k_agg1g2<<<1480, 256>>>(b1, W2, n);              // grid-stride warp/node
    k_agg2<<<gW, 256>>>(b2, out, n);
}

// round 7
// speedup vs baseline: 2.0723x; 1.0978x over previous
#include <cuda_runtime.h>
#include <cuda_bf16.h>
#include <math.h>

// Problem constants (fixed shapes for this bench)
#define NMAX 50000
#define EMAX 800000
#define D    128
#define C    32
#define SCAN_TILE 1024
#define SCAN_MAXB 64   // ceil(NMAX/1024)=49 <= 64

// ---------------- scratch (device globals; no allocation allowed) ----------
// Invariants maintained across calls (all start zero from .bss and are
// restored to zero by construction every call):
//   g_cnt : counted up in k_cnt, counted back down to 0 in k_scatter
//   g_degf: accumulated in k_cnt, read in k_scan, zeroed in k_scatter
//   g_flag: set 1/2 in k_scan, zeroed at the start of k_cnt (next call)
__device__ float g_dis[NMAX];
__device__ int   g_cnt[NMAX];
__device__ float g_degf[NMAX];
__device__ int   g_off[NMAX + 1];
__device__ int   g_flag[SCAN_MAXB];
__device__ int   g_agg[SCAN_MAXB];
__device__ int   g_incv[SCAN_MAXB];
__device__ uint2 g_edge[EMAX];             // {src, bit_cast<uint>(w)}
__device__ float g_h1[(size_t)NMAX * D];   // emb[x] @ W1
__device__ float g_h2[(size_t)NMAX * C];   // relu(agg1)+b1 @ W2  (pre-agg2)

// ---------------- packed f32x2 helpers (sm_103a FFMA2) ---------------------
__device__ __forceinline__ unsigned long long fma2(unsigned long long a,
                                                   unsigned long long b,
                                                   unsigned long long c) {
    unsigned long long d;
    asm("fma.rn.f32x2 %0, %1, %2, %3;" : "=l"(d) : "l"(a), "l"(b), "l"(c));
    return d;
}
__device__ __forceinline__ unsigned long long splat2(float x) {
    unsigned long long d;
    unsigned int b = __float_as_uint(x);
    asm("mov.b64 %0, {%1, %1};" : "=l"(d) : "r"(b));
    return d;
}
__device__ __forceinline__ unsigned long long pack2(float lo, float hi) {
    unsigned long long d;
    asm("mov.b64 %0, {%1, %2};" : "=l"(d) : "f"(lo), "f"(hi));
    return d;
}
__device__ __forceinline__ float lo2(unsigned long long v) {
    return __uint_as_float((unsigned int)v);
}
__device__ __forceinline__ float hi2(unsigned long long v) {
    return __uint_as_float((unsigned int)(v >> 32));
}

// ---------------- kernel 1: counts + weighted degree (+ flag reset) --------
__global__ void k_cnt(const int* __restrict__ col, const float* __restrict__ w,
                      int e) {
    if (blockIdx.x == 0 && threadIdx.x < SCAN_MAXB)
        g_flag[threadIdx.x] = 0;               // reset lookback state
    for (int i = blockIdx.x * blockDim.x + threadIdx.x; i < e;
         i += gridDim.x * blockDim.x) {
        int c = col[i];
        atomicAdd(&g_cnt[c], 1);
        atomicAdd(&g_degf[c], w[i]);
    }
}

// ---------------- kernel 2: single-pass scan (decoupled lookback) + dis ----
__global__ void k_scan(int n, int nb) {
    __shared__ int wsum[8];
    __shared__ int s_exc;
    const int tid = threadIdx.x;           // 256 threads
    const int lane = tid & 31, w = tid >> 5;
    const int b = blockIdx.x;
    const int base = (b * 256 + tid) * 4;

    int4 c = make_int4(0, 0, 0, 0);
    if (base + 3 < n) {
        c = *(const int4*)&g_cnt[base];
    } else if (base < n) {
        c.x = g_cnt[base];
        if (base + 1 < n) c.y = g_cnt[base + 1];
        if (base + 2 < n) c.z = g_cnt[base + 2];
    }
    int s = c.x + c.y + c.z + c.w;

    // inclusive warp scan of per-thread sums
    int v = s;
    #pragma unroll
    for (int o = 1; o < 32; o <<= 1) {
        int t = __shfl_up_sync(0xFFFFFFFFu, v, o);
        if (lane >= o) v += t;
    }
    if (lane == 31) wsum[w] = v;
    __syncthreads();

    if (w == 0) {
        int ws = (lane < 8) ? wsum[lane] : 0;
        #pragma unroll
        for (int o = 1; o < 8; o <<= 1) {
            int t = __shfl_up_sync(0xFFFFFFFFu, ws, o);
            if (lane >= o) ws += t;
        }
        if (lane < 8) wsum[lane] = ws;
        int agg = __shfl_sync(0xFFFFFFFFu, ws, 7);   // block total

        // publish aggregate immediately
        if (lane == 0) {
            atomicExch(&g_agg[b], agg);
            __threadfence();
            atomicExch(&g_flag[b], 1);
        }
        // warp-parallel lookback over predecessors
        int exc = 0;
        int j = b - 1;
        while (j >= 0) {
            int idx = j - lane;
            int f = 0, a = 0;
            if (idx >= 0) {
                do { f = atomicAdd(&g_flag[idx], 0); } while (f == 0);
                a = (f == 2) ? atomicAdd(&g_incv[idx], 0)
                             : atomicAdd(&g_agg[idx], 0);
            }
            unsigned ball = __ballot_sync(0xFFFFFFFFu, idx >= 0 && f == 2);
            if (ball) {
                int first = __ffs(ball) - 1;    // nearest block w/ inclusive
                int contrib = (idx >= 0 && lane <= first) ? a : 0;
                #pragma unroll
                for (int o = 16; o > 0; o >>= 1)
                    contrib += __shfl_xor_sync(0xFFFFFFFFu, contrib, o);
                exc += contrib;
                break;
            } else {
                int contrib = (idx >= 0) ? a : 0;
                #pragma unroll
                for (int o = 16; o > 0; o >>= 1)
                    contrib += __shfl_xor_sync(0xFFFFFFFFu, contrib, o);
                exc += contrib;
                j -= 32;
            }
        }
        if (lane == 0) {
            atomicExch(&g_incv[b], exc + agg);
            __threadfence();
            atomicExch(&g_flag[b], 2);
            s_exc = exc;
        }
    }
    __syncthreads();

    int excl = s_exc + v - s + (w > 0 ? wsum[w - 1] : 0);
    int o0 = excl, o1 = o0 + c.x, o2 = o1 + c.y, o3 = o2 + c.z;
    if (base + 3 < n) {
        *(int4*)&g_off[base] = make_int4(o0, o1, o2, o3);
    } else if (base < n) {
        g_off[base] = o0;
        if (base + 1 < n) g_off[base + 1] = o1;
        if (base + 2 < n) g_off[base + 2] = o2;
    }
    // dis = rsqrt(1 + weighted in-degree)   (self-loop weight 1)
    int lim = min(base + 4, n);
    for (int i = base; i < lim; i++)
        g_dis[i] = rsqrtf(1.0f + g_degf[i]);

    if (b == nb - 1 && tid == 0)
        g_off[n] = s_exc + wsum[7];            // == E
}

// ---------------- kernel 3: scatter (countdown cursor) + degf reset --------
__global__ void k_scatter(const int* __restrict__ row, const int* __restrict__ col,
                          const float* __restrict__ w, int e, int n) {
    int t = blockIdx.x * blockDim.x + threadIdx.x;
    for (int i = t; i < n; i += gridDim.x * blockDim.x)
        g_degf[i] = 0.0f;                      // restore invariant
    for (int i = t; i < e; i += gridDim.x * blockDim.x) {
        int c = col[i];
        int old = atomicSub(&g_cnt[c], 1);     // counts back down to 0
        int pos = g_off[c] + old - 1;
        g_edge[pos] = make_uint2((unsigned)row[i], __float_as_uint(w[i]));
    }
}

// ---------------- kernel 4: fused embedding gather + GEMM1 (f32x2) ---------
#define G1_NODES 64
#define G1_SMEM ((D * D + G1_NODES * D) * sizeof(float))
__global__ void __launch_bounds__(256, 2)
k_gemm1(const int* __restrict__ x, const float* __restrict__ emb,
        const float* __restrict__ W1, int n) {
    extern __shared__ float sm[];
    float* Ws = sm;                 // [D*D]  (64KB)
    float* rows = sm + D * D;       // [64*D] (32KB)
    const int tid  = threadIdx.x;
    const int quad = tid & 31;
    const int ngrp = tid >> 5;

    const float4* W4 = (const float4*)W1;
    float4* Ws4 = (float4*)Ws;
    #pragma unroll
    for (int i = tid; i < D * D / 4; i += 256) Ws4[i] = W4[i];

    bool first = true;
    for (int n0 = blockIdx.x * G1_NODES; n0 < n; n0 += gridDim.x * G1_NODES) {
        if (!first) __syncthreads();
        first = false;

        float4* rows4 = (float4*)rows;
        #pragma unroll
        for (int idx = tid; idx < G1_NODES * (D / 4); idx += 256) {
            int nl = idx >> 5;
            int q  = idx & 31;
            int node = n0 + nl;
            float4 v = make_float4(0.f, 0.f, 0.f, 0.f);
            if (node < n)
                v = ((const float4*)&emb[(size_t)__ldg(&x[node]) * D])[q];
            rows4[idx] = v;
        }
        __syncthreads();

        unsigned long long acc[8][2];
        #pragma unroll
        for (int j = 0; j < 8; j++) { acc[j][0] = 0ULL; acc[j][1] = 0ULL; }

        #pragma unroll 4
        for (int k = 0; k < D; k++) {
            ulonglong2 wv = *(const ulonglong2*)&Ws[k * D + 4 * quad];
            #pragma unroll
            for (int j = 0; j < 8; j++) {
                unsigned long long xs = splat2(rows[(ngrp * 8 + j) * D + k]);
                acc[j][0] = fma2(xs, wv.x, acc[j][0]);
                acc[j][1] = fma2(xs, wv.y, acc[j][1]);
            }
        }
        #pragma unroll
        for (int j = 0; j < 8; j++) {
            int node = n0 + ngrp * 8 + j;
            if (node < n)
                *(ulonglong2*)&g_h1[(size_t)node * D + 4 * quad] =
                    make_ulonglong2(acc[j][0], acc[j][1]);
        }
    }
}

// ---------------- kernel 5: agg1 + bias + relu + GEMM2 (fused, MLP=4) ------
__global__ void __launch_bounds__(256)
k_agg1g2(const float* __restrict__ b1, const float* __restrict__ W2, int n) {
    __shared__ unsigned long long W2p[(D / 2) * C];   // 16KB
    __shared__ __align__(16) float rowsm[8][D];       // 4KB
    const int tid = threadIdx.x;
    const int wl = tid >> 5;
    const int lane = tid & 31;

    for (int i = tid; i < (D / 2) * C; i += 256) {
        int kk = i >> 5, c = i & 31;
        W2p[i] = pack2(W2[(2 * kk) * C + c], W2[(2 * kk + 1) * C + c]);
    }
    __syncthreads();

    float4 bv = *(const float4*)&b1[4 * lane];

    for (int node = blockIdx.x * 8 + wl; node < n; node += gridDim.x * 8) {
        float dn = __ldg(&g_dis[node]);
        float4 acc = *(const float4*)&g_h1[(size_t)node * D + 4 * lane];
        acc.x *= dn; acc.y *= dn; acc.z *= dn; acc.w *= dn;

        int s0 = g_off[node], s1 = g_off[node + 1];
        int e = s0;
        for (; e + 4 <= s1; e += 4) {   // MLP=4
            uint2 e0 = __ldg(&g_edge[e]);
            uint2 e1 = __ldg(&g_edge[e + 1]);
            uint2 e2 = __ldg(&g_edge[e + 2]);
            uint2 e3 = __ldg(&g_edge[e + 3]);
            float n0 = __ldg(&g_dis[e0.x]) * __uint_as_float(e0.y);
            float n1 = __ldg(&g_dis[e1.x]) * __uint_as_float(e1.y);
            float n2 = __ldg(&g_dis[e2.x]) * __uint_as_float(e2.y);
            float n3 = __ldg(&g_dis[e3.x]) * __uint_as_float(e3.y);
            float4 v0 = *(const float4*)&g_h1[(size_t)e0.x * D + 4 * lane];
            float4 v1 = *(const float4*)&g_h1[(size_t)e1.x * D + 4 * lane];
            float4 v2 = *(const float4*)&g_h1[(size_t)e2.x * D + 4 * lane];
            float4 v3 = *(const float4*)&g_h1[(size_t)e3.x * D + 4 * lane];
            acc.x = fmaf(n0, v0.x, acc.x); acc.y = fmaf(n0, v0.y, acc.y);
            acc.z = fmaf(n0, v0.z, acc.z); acc.w = fmaf(n0, v0.w, acc.w);
            acc.x = fmaf(n1, v1.x, acc.x); acc.y = fmaf(n1, v1.y, acc.y);
            acc.z = fmaf(n1, v1.z, acc.z); acc.w = fmaf(n1, v1.w, acc.w);
            acc.x = fmaf(n2, v2.x, acc.x); acc.y = fmaf(n2, v2.y, acc.y);
            acc.z = fmaf(n2, v2.z, acc.z); acc.w = fmaf(n2, v2.w, acc.w);
            acc.x = fmaf(n3, v3.x, acc.x); acc.y = fmaf(n3, v3.y, acc.y);
            acc.z = fmaf(n3, v3.z, acc.z); acc.w = fmaf(n3, v3.w, acc.w);
        }
        for (; e < s1; e++) {
            uint2 ev = __ldg(&g_edge[e]);
            float nm = __ldg(&g_dis[ev.x]) * __uint_as_float(ev.y);
            float4 v = *(const float4*)&g_h1[(size_t)ev.x * D + 4 * lane];
            acc.x = fmaf(nm, v.x, acc.x);
            acc.y = fmaf(nm, v.y, acc.y);
            acc.z = fmaf(nm, v.z, acc.z);
            acc.w = fmaf(nm, v.w, acc.w);
        }
        acc.x = fmaxf(fmaf(dn, acc.x, bv.x), 0.f);
        acc.y = fmaxf(fmaf(dn, acc.y, bv.y), 0.f);
        acc.z = fmaxf(fmaf(dn, acc.z, bv.z), 0.f);
        acc.w = fmaxf(fmaf(dn, acc.w, bv.w), 0.f);

        *(float4*)&rowsm[wl][4 * lane] = acc;
        __syncwarp();

        const unsigned long long* rp = (const unsigned long long*)rowsm[wl];
        unsigned long long a0 = 0ULL, a1 = 0ULL;
        #pragma unroll 8
        for (int kk = 0; kk < D / 2; kk += 2) {
            a0 = fma2(rp[kk],     W2p[kk * C + lane],       a0);
            a1 = fma2(rp[kk + 1], W2p[(kk + 1) * C + lane], a1);
        }
        __syncwarp();
        float h2 = lo2(a0) + hi2(a0) + lo2(a1) + hi2(a1);
        g_h2[(size_t)node * C + lane] = h2;
    }
}

// ---------------- kernel 6: agg2 + bias + log_softmax (MLP=4) --------------
__global__ void k_agg2(const float* __restrict__ b2, float* __restrict__ out, int n) {
    int warp = (blockIdx.x * blockDim.x + threadIdx.x) >> 5;
    int lane = threadIdx.x & 31;
    if (warp >= n) return;
    const int node = warp;

    float dn = __ldg(&g_dis[node]);
    float acc = dn * g_h2[(size_t)node * C + lane];

    int s0 = g_off[node], s1 = g_off[node + 1];
    int e = s0;
    for (; e + 4 <= s1; e += 4) {
        uint2 e0 = __ldg(&g_edge[e]);
        uint2 e1 = __ldg(&g_edge[e + 1]);
        uint2 e2 = __ldg(&g_edge[e + 2]);
        uint2 e3 = __ldg(&g_edge[e + 3]);
        float n0 = __ldg(&g_dis[e0.x]) * __uint_as_float(e0.y);
        float n1 = __ldg(&g_dis[e1.x]) * __uint_as_float(e1.y);
        float n2 = __ldg(&g_dis[e2.x]) * __uint_as_float(e2.y);
        float n3 = __ldg(&g_dis[e3.x]) * __uint_as_float(e3.y);
        float v0 = g_h2[(size_t)e0.x * C + lane];
        float v1 = g_h2[(size_t)e1.x * C + lane];
        float v2 = g_h2[(size_t)e2.x * C + lane];
        float v3 = g_h2[(size_t)e3.x * C + lane];
        acc = fmaf(n0, v0, acc);
        acc = fmaf(n1, v1, acc);
        acc = fmaf(n2, v2, acc);
        acc = fmaf(n3, v3, acc);
    }
    for (; e < s1; e++) {
        uint2 ev = __ldg(&g_edge[e]);
        float nm = __ldg(&g_dis[ev.x]) * __uint_as_float(ev.y);
        acc = fmaf(nm, g_h2[(size_t)ev.x * C + lane], acc);
    }
    acc = fmaf(dn, acc, b2[lane]);

    float m = acc;
    #pragma unroll
    for (int o = 16; o > 0; o >>= 1)
        m = fmaxf(m, __shfl_xor_sync(0xFFFFFFFFu, m, o));
    float ex = __expf(acc - m);
    float s = ex;
    #pragma unroll
    for (int o = 16; o > 0; o >>= 1)
        s += __shfl_xor_sync(0xFFFFFFFFu, s, o);
    out[(size_t)node * C + lane] = acc - m - __logf(s);
}

// ---------------- launch ----------------------------------------------------
extern "C" void kernel_launch(void* const* d_in, const int* in_sizes, int n_in,
                              void* d_out, int out_size) {
    const int*   x   = (const int*)d_in[0];
    const int*   ei  = (const int*)d_in[1];
    const float* ew  = (const float*)d_in[2];
    const float* emb = (const float*)d_in[3];
    const float* W1  = (const float*)d_in[4];
    const float* b1  = (const float*)d_in[5];
    const float* W2  = (const float*)d_in[6];
    const float* b2  = (const float*)d_in[7];
    float* out = (float*)d_out;

    const int n = in_sizes[0];          // 50000
    const int e = in_sizes[2];          // 800000
    const int* row = ei;
    const int* col = ei + e;

    cudaFuncSetAttribute((const void*)k_gemm1,
                         cudaFuncAttributeMaxDynamicSharedMemorySize,
                         (int)G1_SMEM);

    int gE = (e + 255) / 256;
    int gW = (n + 7) / 8;
    int nb = (n + SCAN_TILE - 1) / SCAN_TILE;  // 49

    // Fork gemm1 (independent of CSR preprocessing) onto a side stream.
    // Standard capture-fork pattern: record on origin, wait on side stream.
    // Stream/events are intentionally not destroyed here: destroying them
    // while the harness's capture is still active would invalidate it.
    cudaStream_t s2;
    cudaStreamCreateWithFlags(&s2, cudaStreamNonBlocking);
    cudaEvent_t evA, evB;
    cudaEventCreateWithFlags(&evA, cudaEventDisableTiming);
    cudaEventCreateWithFlags(&evB, cudaEventDisableTiming);

    cudaEventRecord(evA, 0);
    cudaStreamWaitEvent(s2, evA, 0);
    k_gemm1<<<296, 256, G1_SMEM, s2>>>(x, emb, W1, n);
    cudaEventRecord(evB, s2);

    // Preprocessing chain (concurrent with gemm1)
    k_cnt<<<gE, 256>>>(col, ew, e);
    k_scan<<<nb, 256>>>(n, nb);
    k_scatter<<<gE, 256>>>(row, col, ew, e, n);

    // Join, then the dependent tail
    cudaStreamWaitEvent(0, evB, 0);
    k_agg1g2<<<1184, 256>>>(b1, W2, n);
    k_agg2<<<gW, 256>>>(b2, out, n);
}

// round 8
// speedup vs baseline: 2.2918x; 1.1059x over previous
#include <cuda_runtime.h>
#include <cuda_bf16.h>
#include <cuda_fp16.h>
#include <math.h>

// Problem constants (fixed shapes for this bench)
#define NMAX 50000
#define EMAX 800000
#define D    128
#define C    32
#define SCAN_TILE 1024
#define SCAN_MAXB 64   // ceil(NMAX/1024)=49 <= 64

// ---------------- scratch (device globals; no allocation allowed) ----------
// Invariants maintained across calls (all start zero from .bss and are
// restored to zero by construction every call):
//   g_cnt : counted up in k_cnt, counted back down to 0 in k_scatter
//   g_degf: accumulated in k_cnt, read in k_scan, zeroed in k_scatter
//   g_flag: set 1/2 in k_scan, zeroed at the start of k_cnt (next call)
__device__ float  g_dis[NMAX];
__device__ int    g_cnt[NMAX];
__device__ float  g_degf[NMAX];
__device__ int    g_off[NMAX + 1];
__device__ int    g_flag[SCAN_MAXB];
__device__ int    g_agg[SCAN_MAXB];
__device__ int    g_incv[SCAN_MAXB];
__device__ uint2  g_edge[EMAX];              // {src, bit_cast<uint>(w)}
__device__ __half g_h1h[(size_t)NMAX * D];   // emb[x] @ W1      (fp16)
__device__ __half g_h2h[(size_t)NMAX * C];   // relu(agg1)+b1 @ W2 (fp16)

// ---------------- packed f32x2 helpers (sm_103a FFMA2) ---------------------
__device__ __forceinline__ unsigned long long fma2(unsigned long long a,
                                                   unsigned long long b,
                                                   unsigned long long c) {
    unsigned long long d;
    asm("fma.rn.f32x2 %0, %1, %2, %3;" : "=l"(d) : "l"(a), "l"(b), "l"(c));
    return d;
}
__device__ __forceinline__ unsigned long long splat2(float x) {
    unsigned long long d;
    unsigned int b = __float_as_uint(x);
    asm("mov.b64 %0, {%1, %1};" : "=l"(d) : "r"(b));
    return d;
}
__device__ __forceinline__ unsigned long long pack2(float lo, float hi) {
    unsigned long long d;
    asm("mov.b64 %0, {%1, %2};" : "=l"(d) : "f"(lo), "f"(hi));
    return d;
}
__device__ __forceinline__ float lo2(unsigned long long v) {
    return __uint_as_float((unsigned int)v);
}
__device__ __forceinline__ float hi2(unsigned long long v) {
    return __uint_as_float((unsigned int)(v >> 32));
}

// ---------------- kernel 1: counts + weighted degree (+ flag reset) --------
__global__ void k_cnt(const int* __restrict__ col, const float* __restrict__ w,
                      int e) {
    if (blockIdx.x == 0 && threadIdx.x < SCAN_MAXB)
        g_flag[threadIdx.x] = 0;               // reset lookback state
    for (int i = blockIdx.x * blockDim.x + threadIdx.x; i < e;
         i += gridDim.x * blockDim.x) {
        int c = col[i];
        atomicAdd(&g_cnt[c], 1);
        atomicAdd(&g_degf[c], w[i]);
    }
}

// ---------------- kernel 2: single-pass scan (decoupled lookback) + dis ----
__global__ void k_scan(int n, int nb) {
    __shared__ int wsum[8];
    __shared__ int s_exc;
    const int tid = threadIdx.x;           // 256 threads
    const int lane = tid & 31, w = tid >> 5;
    const int b = blockIdx.x;
    const int base = (b * 256 + tid) * 4;

    int4 c = make_int4(0, 0, 0, 0);
    if (base + 3 < n) {
        c = *(const int4*)&g_cnt[base];
    } else if (base < n) {
        c.x = g_cnt[base];
        if (base + 1 < n) c.y = g_cnt[base + 1];
        if (base + 2 < n) c.z = g_cnt[base + 2];
    }
    int s = c.x + c.y + c.z + c.w;

    // inclusive warp scan of per-thread sums
    int v = s;
    #pragma unroll
    for (int o = 1; o < 32; o <<= 1) {
        int t = __shfl_up_sync(0xFFFFFFFFu, v, o);
        if (lane >= o) v += t;
    }
    if (lane == 31) wsum[w] = v;
    __syncthreads();

    if (w == 0) {
        int ws = (lane < 8) ? wsum[lane] : 0;
        #pragma unroll
        for (int o = 1; o < 8; o <<= 1) {
            int t = __shfl_up_sync(0xFFFFFFFFu, ws, o);
            if (lane >= o) ws += t;
        }
        if (lane < 8) wsum[lane] = ws;
        int agg = __shfl_sync(0xFFFFFFFFu, ws, 7);   // block total

        if (lane == 0) {
            atomicExch(&g_agg[b], agg);
            __threadfence();
            atomicExch(&g_flag[b], 1);
        }
        // warp-parallel lookback over predecessors
        int exc = 0;
        int j = b - 1;
        while (j >= 0) {
            int idx = j - lane;
            int f = 0, a = 0;
            if (idx >= 0) {
                do { f = atomicAdd(&g_flag[idx], 0); } while (f == 0);
                a = (f == 2) ? atomicAdd(&g_incv[idx], 0)
                             : atomicAdd(&g_agg[idx], 0);
            }
            unsigned ball = __ballot_sync(0xFFFFFFFFu, idx >= 0 && f == 2);
            if (ball) {
                int first = __ffs(ball) - 1;
                int contrib = (idx >= 0 && lane <= first) ? a : 0;
                #pragma unroll
                for (int o = 16; o > 0; o >>= 1)
                    contrib += __shfl_xor_sync(0xFFFFFFFFu, contrib, o);
                exc += contrib;
                break;
            } else {
                int contrib = (idx >= 0) ? a : 0;
                #pragma unroll
                for (int o = 16; o > 0; o >>= 1)
                    contrib += __shfl_xor_sync(0xFFFFFFFFu, contrib, o);
                exc += contrib;
                j -= 32;
            }
        }
        if (lane == 0) {
            atomicExch(&g_incv[b], exc + agg);
            __threadfence();
            atomicExch(&g_flag[b], 2);
            s_exc = exc;
        }
    }
    __syncthreads();

    int excl = s_exc + v - s + (w > 0 ? wsum[w - 1] : 0);
    int o0 = excl, o1 = o0 + c.x, o2 = o1 + c.y, o3 = o2 + c.z;
    if (base + 3 < n) {
        *(int4*)&g_off[base] = make_int4(o0, o1, o2, o3);
    } else if (base < n) {
        g_off[base] = o0;
        if (base + 1 < n) g_off[base + 1] = o1;
        if (base + 2 < n) g_off[base + 2] = o2;
    }
    // dis = rsqrt(1 + weighted in-degree)   (self-loop weight 1)
    int lim = min(base + 4, n);
    for (int i = base; i < lim; i++)
        g_dis[i] = rsqrtf(1.0f + g_degf[i]);

    if (b == nb - 1 && tid == 0)
        g_off[n] = s_exc + wsum[7];            // == E
}

// ---------------- kernel 3: scatter (countdown cursor) + degf reset --------
__global__ void k_scatter(const int* __restrict__ row, const int* __restrict__ col,
                          const float* __restrict__ w, int e, int n) {
    int t = blockIdx.x * blockDim.x + threadIdx.x;
    for (int i = t; i < n; i += gridDim.x * blockDim.x)
        g_degf[i] = 0.0f;                      // restore invariant
    for (int i = t; i < e; i += gridDim.x * blockDim.x) {
        int c = col[i];
        int old = atomicSub(&g_cnt[c], 1);     // counts back down to 0
        int pos = g_off[c] + old - 1;
        g_edge[pos] = make_uint2((unsigned)row[i], __float_as_uint(w[i]));
    }
}

// ---------------- kernel 4: fused embedding gather + GEMM1 -> fp16 ---------
#define G1_NODES 64
#define G1_SMEM ((D * D + G1_NODES * D) * sizeof(float))
__global__ void __launch_bounds__(256, 2)
k_gemm1(const int* __restrict__ x, const float* __restrict__ emb,
        const float* __restrict__ W1, int n) {
    extern __shared__ float sm[];
    float* Ws = sm;                 // [D*D]  (64KB)
    float* rows = sm + D * D;       // [64*D] (32KB)
    const int tid  = threadIdx.x;
    const int quad = tid & 31;
    const int ngrp = tid >> 5;

    const float4* W4 = (const float4*)W1;
    float4* Ws4 = (float4*)Ws;
    #pragma unroll
    for (int i = tid; i < D * D / 4; i += 256) Ws4[i] = W4[i];

    bool first = true;
    for (int n0 = blockIdx.x * G1_NODES; n0 < n; n0 += gridDim.x * G1_NODES) {
        if (!first) __syncthreads();
        first = false;

        float4* rows4 = (float4*)rows;
        #pragma unroll
        for (int idx = tid; idx < G1_NODES * (D / 4); idx += 256) {
            int nl = idx >> 5;
            int q  = idx & 31;
            int node = n0 + nl;
            float4 v = make_float4(0.f, 0.f, 0.f, 0.f);
            if (node < n)
                v = ((const float4*)&emb[(size_t)__ldg(&x[node]) * D])[q];
            rows4[idx] = v;
        }
        __syncthreads();

        unsigned long long acc[8][2];
        #pragma unroll
        for (int j = 0; j < 8; j++) { acc[j][0] = 0ULL; acc[j][1] = 0ULL; }

        #pragma unroll 4
        for (int k = 0; k < D; k++) {
            ulonglong2 wv = *(const ulonglong2*)&Ws[k * D + 4 * quad];
            #pragma unroll
            for (int j = 0; j < 8; j++) {
                unsigned long long xs = splat2(rows[(ngrp * 8 + j) * D + k]);
                acc[j][0] = fma2(xs, wv.x, acc[j][0]);
                acc[j][1] = fma2(xs, wv.y, acc[j][1]);
            }
        }
        #pragma unroll
        for (int j = 0; j < 8; j++) {
            int node = n0 + ngrp * 8 + j;
            if (node < n) {
                __half2 h01 = __floats2half2_rn(lo2(acc[j][0]), hi2(acc[j][0]));
                __half2 h23 = __floats2half2_rn(lo2(acc[j][1]), hi2(acc[j][1]));
                uint2 st = make_uint2(*(unsigned*)&h01, *(unsigned*)&h23);
                *(uint2*)&g_h1h[(size_t)node * D + 4 * quad] = st;
            }
        }
    }
}

// ---------------- fp16 gather helper: 4 halves -> fma into float4 acc ------
__device__ __forceinline__ void fma_row_h(float4& acc, float nm,
                                          const __half* __restrict__ p) {
    uint2 hv = __ldg((const uint2*)p);
    float2 f0 = __half22float2(*(const __half2*)&hv.x);
    float2 f1 = __half22float2(*(const __half2*)&hv.y);
    acc.x = fmaf(nm, f0.x, acc.x);
    acc.y = fmaf(nm, f0.y, acc.y);
    acc.z = fmaf(nm, f1.x, acc.z);
    acc.w = fmaf(nm, f1.y, acc.w);
}

// ---------------- kernel 5: agg1 + bias + relu + GEMM2 (fused, MLP=4) ------
__global__ void __launch_bounds__(256)
k_agg1g2(const float* __restrict__ b1, const float* __restrict__ W2, int n) {
    __shared__ unsigned long long W2p[(D / 2) * C];   // 16KB
    __shared__ __align__(16) float rowsm[8][D];       // 4KB
    const int tid = threadIdx.x;
    const int wl = tid >> 5;
    const int lane = tid & 31;

    for (int i = tid; i < (D / 2) * C; i += 256) {
        int kk = i >> 5, c = i & 31;
        W2p[i] = pack2(W2[(2 * kk) * C + c], W2[(2 * kk + 1) * C + c]);
    }
    __syncthreads();

    float4 bv = *(const float4*)&b1[4 * lane];

    for (int node = blockIdx.x * 8 + wl; node < n; node += gridDim.x * 8) {
        float dn = __ldg(&g_dis[node]);
        float4 acc = make_float4(0.f, 0.f, 0.f, 0.f);
        fma_row_h(acc, dn, &g_h1h[(size_t)node * D + 4 * lane]);  // self term

        int s0 = g_off[node], s1 = g_off[node + 1];
        int e = s0;
        for (; e + 4 <= s1; e += 4) {   // MLP=4: batch independent loads
            uint2 e0 = __ldg(&g_edge[e]);
            uint2 e1 = __ldg(&g_edge[e + 1]);
            uint2 e2 = __ldg(&g_edge[e + 2]);
            uint2 e3 = __ldg(&g_edge[e + 3]);
            float n0 = __ldg(&g_dis[e0.x]) * __uint_as_float(e0.y);
            float n1 = __ldg(&g_dis[e1.x]) * __uint_as_float(e1.y);
            float n2 = __ldg(&g_dis[e2.x]) * __uint_as_float(e2.y);
            float n3 = __ldg(&g_dis[e3.x]) * __uint_as_float(e3.y);
            fma_row_h(acc, n0, &g_h1h[(size_t)e0.x * D + 4 * lane]);
            fma_row_h(acc, n1, &g_h1h[(size_t)e1.x * D + 4 * lane]);
            fma_row_h(acc, n2, &g_h1h[(size_t)e2.x * D + 4 * lane]);
            fma_row_h(acc, n3, &g_h1h[(size_t)e3.x * D + 4 * lane]);
        }
        for (; e < s1; e++) {
            uint2 ev = __ldg(&g_edge[e]);
            float nm = __ldg(&g_dis[ev.x]) * __uint_as_float(ev.y);
            fma_row_h(acc, nm, &g_h1h[(size_t)ev.x * D + 4 * lane]);
        }
        acc.x = fmaxf(fmaf(dn, acc.x, bv.x), 0.f);
        acc.y = fmaxf(fmaf(dn, acc.y, bv.y), 0.f);
        acc.z = fmaxf(fmaf(dn, acc.z, bv.z), 0.f);
        acc.w = fmaxf(fmaf(dn, acc.w, bv.w), 0.f);

        *(float4*)&rowsm[wl][4 * lane] = acc;
        __syncwarp();

        const unsigned long long* rp = (const unsigned long long*)rowsm[wl];
        unsigned long long a0 = 0ULL, a1 = 0ULL;
        #pragma unroll 8
        for (int kk = 0; kk < D / 2; kk += 2) {
            a0 = fma2(rp[kk],     W2p[kk * C + lane],       a0);
            a1 = fma2(rp[kk + 1], W2p[(kk + 1) * C + lane], a1);
        }
        __syncwarp();
        float h2 = lo2(a0) + hi2(a0) + lo2(a1) + hi2(a1);
        g_h2h[(size_t)node * C + lane] = __float2half_rn(h2);
    }
}

// ---------------- kernel 6: agg2 + bias + log_softmax (MLP=4) --------------
__global__ void k_agg2(const float* __restrict__ b2, float* __restrict__ out, int n) {
    int warp = (blockIdx.x * blockDim.x + threadIdx.x) >> 5;
    int lane = threadIdx.x & 31;
    if (warp >= n) return;
    const int node = warp;

    float dn = __ldg(&g_dis[node]);
    float acc = dn * __half2float(g_h2h[(size_t)node * C + lane]);

    int s0 = g_off[node], s1 = g_off[node + 1];
    int e = s0;
    for (; e + 4 <= s1; e += 4) {
        uint2 e0 = __ldg(&g_edge[e]);
        uint2 e1 = __ldg(&g_edge[e + 1]);
        uint2 e2 = __ldg(&g_edge[e + 2]);
        uint2 e3 = __ldg(&g_edge[e + 3]);
        float n0 = __ldg(&g_dis[e0.x]) * __uint_as_float(e0.y);
        float n1 = __ldg(&g_dis[e1.x]) * __uint_as_float(e1.y);
        float n2 = __ldg(&g_dis[e2.x]) * __uint_as_float(e2.y);
        float n3 = __ldg(&g_dis[e3.x]) * __uint_as_float(e3.y);
        float v0 = __half2float(__ldg(&g_h2h[(size_t)e0.x * C + lane]));
        float v1 = __half2float(__ldg(&g_h2h[(size_t)e1.x * C + lane]));
        float v2 = __half2float(__ldg(&g_h2h[(size_t)e2.x * C + lane]));
        float v3 = __half2float(__ldg(&g_h2h[(size_t)e3.x * C + lane]));
        acc = fmaf(n0, v0, acc);
        acc = fmaf(n1, v1, acc);
        acc = fmaf(n2, v2, acc);
        acc = fmaf(n3, v3, acc);
    }
    for (; e < s1; e++) {
        uint2 ev = __ldg(&g_edge[e]);
        float nm = __ldg(&g_dis[ev.x]) * __uint_as_float(ev.y);
        acc = fmaf(nm, __half2float(__ldg(&g_h2h[(size_t)ev.x * C + lane])), acc);
    }
    acc = fmaf(dn, acc, b2[lane]);

    float m = acc;
    #pragma unroll
    for (int o = 16; o > 0; o >>= 1)
        m = fmaxf(m, __shfl_xor_sync(0xFFFFFFFFu, m, o));
    float ex = __expf(acc - m);
    float s = ex;
    #pragma unroll
    for (int o = 16; o > 0; o >>= 1)
        s += __shfl_xor_sync(0xFFFFFFFFu, s, o);
    out[(size_t)node * C + lane] = acc - m - __logf(s);
}

// ---------------- launch ----------------------------------------------------
extern "C" void kernel_launch(void* const* d_in, const int* in_sizes, int n_in,
                              void* d_out, int out_size) {
    const int*   x   = (const int*)d_in[0];
    const int*   ei  = (const int*)d_in[1];
    const float* ew  = (const float*)d_in[2];
    const float* emb = (const float*)d_in[3];
    const float* W1  = (const float*)d_in[4];
    const float* b1  = (const float*)d_in[5];
    const float* W2  = (const float*)d_in[6];
    const float* b2  = (const float*)d_in[7];
    float* out = (float*)d_out;

    const int n = in_sizes[0];          // 50000
    const int e = in_sizes[2];          // 800000
    const int* row = ei;
    const int* col = ei + e;

    cudaFuncSetAttribute((const void*)k_gemm1,
                         cudaFuncAttributeMaxDynamicSharedMemorySize,
                         (int)G1_SMEM);

    int gE = (e + 255) / 256;
    int gW = (n + 7) / 8;
    int nb = (n + SCAN_TILE - 1) / SCAN_TILE;  // 49

    // Fork gemm1 (independent of CSR preprocessing) onto a side stream.
    // Stream/events intentionally not destroyed (capture-safe).
    cudaStream_t s2;
    cudaStreamCreateWithFlags(&s2, cudaStreamNonBlocking);
    cudaEvent_t evA, evB;
    cudaEventCreateWithFlags(&evA, cudaEventDisableTiming);
    cudaEventCreateWithFlags(&evB, cudaEventDisableTiming);

    cudaEventRecord(evA, 0);
    cudaStreamWaitEvent(s2, evA, 0);
    k_gemm1<<<296, 256, G1_SMEM, s2>>>(x, emb, W1, n);
    cudaEventRecord(evB, s2);

    // Preprocessing chain (concurrent with gemm1)
    k_cnt<<<gE, 256>>>(col, ew, e);
    k_scan<<<nb, 256>>>(n, nb);
    k_scatter<<<gE, 256>>>(row, col, ew, e, n);

    // Join, then the dependent tail
    cudaStreamWaitEvent(0, evB, 0);
    k_agg1g2<<<1184, 256>>>(b1, W2, n);
    k_agg2<<<gW, 256>>>(b2, out, n);
}